// round 13
// baseline (speedup 1.0000x reference)
#include <cuda_runtime.h>
#include <math.h>
#include <stdint.h>

#define EXPERTS 8
#define HID     2048
#define IEXP    1408
#define SIEXP   2816
#define TTOK    4096
#define NPAIR   8192

// ---------------- scratch ----------------
__device__ int   g_cnt[EXPERTS];
__device__ int   g_tok[EXPERTS * NPAIR];
__device__ int   g_pid[EXPERTS * NPAIR];
__device__ float g_pw [EXPERTS * NPAIR];
__device__ float g_act[11534336];        // [TTOK][SIEXP] then [NPAIR][IEXP]
__device__ float g_pairout[NPAIR * HID];
// tf32-prerounded copies of inputs
__device__ float g_xr  [TTOK * HID];
__device__ float g_w1r [EXPERTS * HID * 2 * IEXP];
__device__ float g_w2r [EXPERTS * IEXP * HID];
__device__ float g_ws1r[HID * 2 * SIEXP];
__device__ float g_ws2r[SIEXP * HID];

__device__ __forceinline__ float silu_f(float a) { return a / (1.0f + expf(-a)); }

__device__ __forceinline__ uint32_t f2t(float x) {
    uint32_t r; asm("cvt.rna.tf32.f32 %0, %1;" : "=r"(r) : "f"(x)); return r;
}
__device__ __forceinline__ float f2tf(float x) { return __uint_as_float(f2t(x)); }

__device__ __forceinline__ void mma8(float& d0, float& d1, float& d2, float& d3,
                                     uint32_t a0, uint32_t a1, uint32_t a2, uint32_t a3,
                                     uint32_t b0, uint32_t b1) {
    asm volatile(
        "mma.sync.aligned.m16n8k8.row.col.f32.tf32.tf32.f32 "
        "{%0,%1,%2,%3},{%4,%5,%6,%7},{%8,%9},{%0,%1,%2,%3};"
        : "+f"(d0), "+f"(d1), "+f"(d2), "+f"(d3)
        : "r"(a0), "r"(a1), "r"(a2), "r"(a3), "r"(b0), "r"(b1));
}

__device__ __forceinline__ void cpa16(void* dst_smem, const void* src) {
    uint32_t d = (uint32_t)__cvta_generic_to_shared(dst_smem);
    asm volatile("cp.async.cg.shared.global [%0], [%1], 16;" :: "r"(d), "l"(src));
}
#define CP_COMMIT() asm volatile("cp.async.commit_group;")
#define CP_WAIT(N)  asm volatile("cp.async.wait_group %0;" :: "n"(N))

// ---------------- pre-round to tf32 ----------------
__global__ void round_tf32_kernel(const float4* __restrict__ src,
                                  float4* __restrict__ dst, int n4) {
    int i = blockIdx.x * blockDim.x + threadIdx.x;
    if (i < n4) {
        float4 v = src[i];
        v.x = f2tf(v.x); v.y = f2tf(v.y); v.z = f2tf(v.z); v.w = f2tf(v.w);
        dst[i] = v;
    }
}

// ---------------- routing ----------------
__global__ void zero_cnt_kernel() {
    if (threadIdx.x < EXPERTS) g_cnt[threadIdx.x] = 0;
}

__global__ void route_kernel(const int* __restrict__ topk_idx,
                             const float* __restrict__ topk_w) {
    int p = blockIdx.x * blockDim.x + threadIdx.x;
    if (p < NPAIR) {
        int e = topk_idx[p];
        int pos = atomicAdd(&g_cnt[e], 1);
        g_tok[e * NPAIR + pos] = p >> 1;
        g_pid[e * NPAIR + pos] = p;
        g_pw [e * NPAIR + pos] = topk_w[p];
    }
}

// =====================================================================
// GEMM1: h = silu(A @ Wg) * (A @ Wu). 256 threads, 8 warps = 4(M) x 2(N).
// CTA 128x64 per half. Warp: 32(M) x 32(N) per half.
// 2-stage cp.async ring -> 73.7KB/CTA so __launch_bounds__(256,2) truly
// yields 2 CTAs/SM (R12's 3-stage ring didn't fit; occupancy stayed 1).
// buffer: As 128*36, Ba 32*72, Bb 32*72 (uint32) = 36864 B
// =====================================================================
#define G1_BUF (36864)
template<int ROUTED>
__global__ __launch_bounds__(256, 2) void gemm1_tpl(const float* __restrict__ X,
                                                    const float* __restrict__ Wfull) {
    const int IN  = ROUTED ? IEXP : SIEXP;
    const int ldw = 2 * IN;
    const int m0 = blockIdx.y * 128;
    const int n0 = blockIdx.x * 64;

    extern __shared__ char dsm[];
    __shared__ int s_tok[128];
    __shared__ int s_pid[128];

    const int tid = threadIdx.x;
    const float* W = Wfull;
    if (ROUTED) {
        const int e = blockIdx.z;
        const int cnt = g_cnt[e];
        if (m0 >= cnt) return;
        W += (size_t)e * HID * ldw;
        if (tid < 128) {
            int r = m0 + tid;
            bool ok = r < cnt;
            s_tok[tid] = ok ? g_tok[e * NPAIR + r] : 0;
            s_pid[tid] = ok ? g_pid[e * NPAIR + r] : -1;
        }
        __syncthreads();
    }

    const int lane = tid & 31, w = tid >> 5;
    const int gid = lane >> 2, tig = lane & 3;
    const int wm = w & 3, wn = w >> 2;

    int a_m[4];
    #pragma unroll
    for (int p = 0; p < 4; p++) {
        int m = (p * 256 + tid) >> 3;
        a_m[p] = ROUTED ? s_tok[m] : (m0 + m);
    }

    float accA[2][4][4] = {}, accB[2][4][4] = {};

    #define G1_ISSUE(buf, k0)                                                        \
    {                                                                                \
        uint32_t* As = (uint32_t*)(dsm + (buf) * G1_BUF);                            \
        uint32_t* Ba = (uint32_t*)(dsm + (buf) * G1_BUF + 18432);                    \
        uint32_t* Bb = (uint32_t*)(dsm + (buf) * G1_BUF + 27648);                    \
        _Pragma("unroll")                                                            \
        for (int p = 0; p < 4; p++) {                                                \
            int idx = p * 256 + tid;                                                 \
            int m = idx >> 3, k4 = (idx & 7) << 2;                                   \
            cpa16(&As[m * 36 + k4], &X[(size_t)a_m[p] * HID + (k0) + k4]);           \
        }                                                                            \
        _Pragma("unroll")                                                            \
        for (int p = 0; p < 2; p++) {                                                \
            int idx = p * 256 + tid;                                                 \
            int kr = idx >> 4, nc = (idx & 15) << 2;                                 \
            cpa16(&Ba[kr * 72 + nc], &W[(size_t)((k0) + kr) * ldw + n0 + nc]);       \
            cpa16(&Bb[kr * 72 + nc], &W[(size_t)((k0) + kr) * ldw + IN + n0 + nc]);  \
        }                                                                            \
        CP_COMMIT();                                                                 \
    }

    G1_ISSUE(0, 0);
    G1_ISSUE(1, 32);

    int buf = 0;
    for (int k0 = 0; k0 < HID; k0 += 32) {
        CP_WAIT(1);            // stage for this iteration resident
        __syncthreads();

        const uint32_t* As = (const uint32_t*)(dsm + buf * G1_BUF);
        const uint32_t* Ba = (const uint32_t*)(dsm + buf * G1_BUF + 18432);
        const uint32_t* Bb = (const uint32_t*)(dsm + buf * G1_BUF + 27648);

        #pragma unroll
        for (int ks = 0; ks < 4; ks++) {
            const int kk = ks * 8;
            uint32_t af[2][4];
            #pragma unroll
            for (int mt = 0; mt < 2; mt++) {
                int mr = wm * 32 + mt * 16;
                af[mt][0] = As[(mr + gid    ) * 36 + kk + tig];
                af[mt][1] = As[(mr + gid + 8) * 36 + kk + tig];
                af[mt][2] = As[(mr + gid    ) * 36 + kk + tig + 4];
                af[mt][3] = As[(mr + gid + 8) * 36 + kk + tig + 4];
            }
            #pragma unroll
            for (int nt = 0; nt < 4; nt++) {
                int nb = wn * 32 + nt * 8 + gid;
                uint32_t ba0 = Ba[(kk + tig) * 72 + nb], ba1 = Ba[(kk + tig + 4) * 72 + nb];
                uint32_t bb0 = Bb[(kk + tig) * 72 + nb], bb1 = Bb[(kk + tig + 4) * 72 + nb];
                #pragma unroll
                for (int mt = 0; mt < 2; mt++) {
                    mma8(accA[mt][nt][0], accA[mt][nt][1], accA[mt][nt][2], accA[mt][nt][3],
                         af[mt][0], af[mt][1], af[mt][2], af[mt][3], ba0, ba1);
                    mma8(accB[mt][nt][0], accB[mt][nt][1], accB[mt][nt][2], accB[mt][nt][3],
                         af[mt][0], af[mt][1], af[mt][2], af[mt][3], bb0, bb1);
                }
            }
        }
        __syncthreads();       // all warps done reading buf before refill

        int kn = k0 + 64;
        if (kn < HID) { G1_ISSUE(buf, kn); }
        else          { CP_COMMIT(); }      // keep wait-count uniform
        buf ^= 1;
    }
    #undef G1_ISSUE

    // epilogue: swiglu (rounded to tf32 for next GEMM), write g_act
    #pragma unroll
    for (int mt = 0; mt < 2; mt++) {
        int lm0 = wm * 32 + mt * 16 + gid;
        int lm1 = lm0 + 8;
        int row0, row1;
        if (ROUTED) { row0 = s_pid[lm0]; row1 = s_pid[lm1]; }
        else        { row0 = m0 + lm0;   row1 = m0 + lm1; }
        #pragma unroll
        for (int nt = 0; nt < 4; nt++) {
            int col = n0 + wn * 32 + nt * 8 + 2 * tig;
            if (row0 >= 0) {
                float2 v;
                v.x = f2tf(silu_f(accA[mt][nt][0]) * accB[mt][nt][0]);
                v.y = f2tf(silu_f(accA[mt][nt][1]) * accB[mt][nt][1]);
                *(float2*)&g_act[(size_t)row0 * IN + col] = v;
            }
            if (row1 >= 0) {
                float2 v;
                v.x = f2tf(silu_f(accA[mt][nt][2]) * accB[mt][nt][2]);
                v.y = f2tf(silu_f(accA[mt][nt][3]) * accB[mt][nt][3]);
                *(float2*)&g_act[(size_t)row1 * IN + col] = v;
            }
        }
    }
}

// =====================================================================
// GEMM2: C = act @ W. 256 threads, 8 warps = 2(M) x 4(N).
// CTA 128x128. Warp: 64(M) x 32(N). 2-stage cp.async ring, 2 CTAs/SM.
// buffer: As 128*36, Bs 32*136 (uint32) = 35840 B
// =====================================================================
#define G2_BUF (35840)
template<int ROUTED>
__global__ __launch_bounds__(256, 2) void gemm2_tpl(const float* __restrict__ Wfull,
                                                    float* __restrict__ C) {
    const int IN = ROUTED ? IEXP : SIEXP;   // K dim
    const int m0 = blockIdx.y * 128;
    const int n0 = blockIdx.x * 128;

    extern __shared__ char dsm[];
    __shared__ int   s_pid[128];
    __shared__ float s_w[128];

    const int tid = threadIdx.x;
    const float* W = Wfull;
    float* Cw = ROUTED ? g_pairout : C;
    if (ROUTED) {
        const int e = blockIdx.z;
        const int cnt = g_cnt[e];
        if (m0 >= cnt) return;
        W += (size_t)e * IEXP * HID;
        if (tid < 128) {
            int r = m0 + tid;
            bool ok = r < cnt;
            s_pid[tid] = ok ? g_pid[e * NPAIR + r] : -1;
            s_w[tid]   = ok ? g_pw [e * NPAIR + r] : 0.f;
        }
        __syncthreads();
    }

    const int lane = tid & 31, w = tid >> 5;
    const int gid = lane >> 2, tig = lane & 3;
    const int wm = w & 1, wn = w >> 1;

    int a_m[4];
    #pragma unroll
    for (int p = 0; p < 4; p++) {
        int m = (p * 256 + tid) >> 3;
        a_m[p] = ROUTED ? (s_pid[m] >= 0 ? s_pid[m] : 0) : (m0 + m);
    }

    float acc[4][4][4] = {};

    #define G2_ISSUE(buf, k0)                                                      \
    {                                                                              \
        uint32_t* As = (uint32_t*)(dsm + (buf) * G2_BUF);                          \
        uint32_t* Bs = (uint32_t*)(dsm + (buf) * G2_BUF + 18432);                  \
        _Pragma("unroll")                                                          \
        for (int p = 0; p < 4; p++) {                                              \
            int idx = p * 256 + tid;                                               \
            int m = idx >> 3, k4 = (idx & 7) << 2;                                 \
            cpa16(&As[m * 36 + k4], &g_act[(size_t)a_m[p] * IN + (k0) + k4]);      \
        }                                                                          \
        _Pragma("unroll")                                                          \
        for (int p = 0; p < 4; p++) {                                              \
            int idx = p * 256 + tid;                                               \
            int kr = idx >> 5, nc = (idx & 31) << 2;                               \
            cpa16(&Bs[kr * 136 + nc], &W[(size_t)((k0) + kr) * HID + n0 + nc]);    \
        }                                                                          \
        CP_COMMIT();                                                               \
    }

    G2_ISSUE(0, 0);
    G2_ISSUE(1, 32);

    int buf = 0;
    for (int k0 = 0; k0 < IN; k0 += 32) {
        CP_WAIT(1);
        __syncthreads();

        const uint32_t* As = (const uint32_t*)(dsm + buf * G2_BUF);
        const uint32_t* Bs = (const uint32_t*)(dsm + buf * G2_BUF + 18432);

        #pragma unroll
        for (int ks = 0; ks < 4; ks++) {
            const int kk = ks * 8;
            uint32_t af[4][4];
            #pragma unroll
            for (int mt = 0; mt < 4; mt++) {
                int mr = wm * 64 + mt * 16;
                af[mt][0] = As[(mr + gid    ) * 36 + kk + tig];
                af[mt][1] = As[(mr + gid + 8) * 36 + kk + tig];
                af[mt][2] = As[(mr + gid    ) * 36 + kk + tig + 4];
                af[mt][3] = As[(mr + gid + 8) * 36 + kk + tig + 4];
            }
            #pragma unroll
            for (int nt = 0; nt < 4; nt++) {
                int nb = wn * 32 + nt * 8 + gid;
                uint32_t b0 = Bs[(kk + tig) * 136 + nb], b1 = Bs[(kk + tig + 4) * 136 + nb];
                #pragma unroll
                for (int mt = 0; mt < 4; mt++)
                    mma8(acc[mt][nt][0], acc[mt][nt][1], acc[mt][nt][2], acc[mt][nt][3],
                         af[mt][0], af[mt][1], af[mt][2], af[mt][3], b0, b1);
            }
        }
        __syncthreads();

        int kn = k0 + 64;
        if (kn < IN) { G2_ISSUE(buf, kn); }
        else         { CP_COMMIT(); }
        buf ^= 1;
    }
    #undef G2_ISSUE

    // epilogue
    #pragma unroll
    for (int mt = 0; mt < 4; mt++) {
        int lm0 = wm * 64 + mt * 16 + gid;
        int lm1 = lm0 + 8;
        int row0, row1; float w0 = 1.f, w1 = 1.f;
        if (ROUTED) {
            row0 = s_pid[lm0]; row1 = s_pid[lm1];
            w0 = s_w[lm0]; w1 = s_w[lm1];
        } else { row0 = m0 + lm0; row1 = m0 + lm1; }
        #pragma unroll
        for (int nt = 0; nt < 4; nt++) {
            int col = n0 + wn * 32 + nt * 8 + 2 * tig;
            if (row0 >= 0) {
                float2 v; v.x = w0 * acc[mt][nt][0]; v.y = w0 * acc[mt][nt][1];
                *(float2*)&Cw[(size_t)row0 * HID + col] = v;
            }
            if (row1 >= 0) {
                float2 v; v.x = w1 * acc[mt][nt][2]; v.y = w1 * acc[mt][nt][3];
                *(float2*)&Cw[(size_t)row1 * HID + col] = v;
            }
        }
    }
}

// ---------------- combine ----------------
__global__ void combine_kernel(float* __restrict__ out) {
    int v = blockIdx.x * blockDim.x + threadIdx.x;
    const int HV = HID / 4;
    if (v < TTOK * HV) {
        int t = v / HV;
        int h4 = v - t * HV;
        float4 o  = ((float4*)out)[v];
        float4 p0 = ((const float4*)g_pairout)[(size_t)(2 * t) * HV + h4];
        float4 p1 = ((const float4*)g_pairout)[(size_t)(2 * t + 1) * HV + h4];
        o.x += p0.x + p1.x; o.y += p0.y + p1.y;
        o.z += p0.z + p1.z; o.w += p0.w + p1.w;
        ((float4*)out)[v] = o;
    }
}

// ---------------- launcher ----------------
extern "C" void kernel_launch(void* const* d_in, const int* in_sizes, int n_in,
                              void* d_out, int out_size) {
    const float* x        = (const float*)d_in[0];  // [T, H]
    const float* topk_w   = (const float*)d_in[1];  // [T, 2]
    const float* W1       = (const float*)d_in[2];  // [E, H, 2I]
    const float* W2       = (const float*)d_in[3];  // [E, I, H]
    const float* Ws1      = (const float*)d_in[4];  // [H, 2SI]
    const float* Ws2      = (const float*)d_in[5];  // [SI, H]
    const int*   topk_idx = (const int*)d_in[6];    // [T, 2]
    float* out = (float*)d_out;                     // [T, H]

    (void)in_sizes; (void)n_in; (void)out_size;

    float *xr, *w1r, *w2r, *ws1r, *ws2r;
    cudaGetSymbolAddress((void**)&xr,   g_xr);
    cudaGetSymbolAddress((void**)&w1r,  g_w1r);
    cudaGetSymbolAddress((void**)&w2r,  g_w2r);
    cudaGetSymbolAddress((void**)&ws1r, g_ws1r);
    cudaGetSymbolAddress((void**)&ws2r, g_ws2r);

    cudaFuncSetAttribute(gemm1_tpl<0>, cudaFuncAttributeMaxDynamicSharedMemorySize, 2 * G1_BUF);
    cudaFuncSetAttribute(gemm1_tpl<1>, cudaFuncAttributeMaxDynamicSharedMemorySize, 2 * G1_BUF);
    cudaFuncSetAttribute(gemm2_tpl<0>, cudaFuncAttributeMaxDynamicSharedMemorySize, 2 * G2_BUF);
    cudaFuncSetAttribute(gemm2_tpl<1>, cudaFuncAttributeMaxDynamicSharedMemorySize, 2 * G2_BUF);

    // pre-round inputs to tf32
    const int n4x   = TTOK * HID / 4;
    const int n4w1  = EXPERTS * HID * 2 * IEXP / 4;
    const int n4w2  = EXPERTS * IEXP * HID / 4;
    const int n4ws1 = HID * 2 * SIEXP / 4;
    const int n4ws2 = SIEXP * HID / 4;
    round_tf32_kernel<<<(n4x   + 255) / 256, 256>>>((const float4*)x,   (float4*)xr,   n4x);
    round_tf32_kernel<<<(n4w1  + 255) / 256, 256>>>((const float4*)W1,  (float4*)w1r,  n4w1);
    round_tf32_kernel<<<(n4w2  + 255) / 256, 256>>>((const float4*)W2,  (float4*)w2r,  n4w2);
    round_tf32_kernel<<<(n4ws1 + 255) / 256, 256>>>((const float4*)Ws1, (float4*)ws1r, n4ws1);
    round_tf32_kernel<<<(n4ws2 + 255) / 256, 256>>>((const float4*)Ws2, (float4*)ws2r, n4ws2);

    zero_cnt_kernel<<<1, 32>>>();
    route_kernel<<<NPAIR / 256, 256>>>(topk_idx, topk_w);

    // shared expert path
    gemm1_tpl<0><<<dim3(SIEXP / 64, TTOK / 128), 256, 2 * G1_BUF>>>(xr, ws1r);
    gemm2_tpl<0><<<dim3(HID / 128, TTOK / 128), 256, 2 * G2_BUF>>>(ws2r, out);

    // routed expert path (g_act reused after shared GEMM2 consumed it)
    gemm1_tpl<1><<<dim3(IEXP / 64, NPAIR / 128, EXPERTS), 256, 2 * G1_BUF>>>(xr, w1r);
    gemm2_tpl<1><<<dim3(HID / 128, NPAIR / 128, EXPERTS), 256, 2 * G2_BUF>>>(w2r, nullptr);

    combine_kernel<<<(TTOK * (HID / 4) + 255) / 256, 256>>>(out);
}

// round 16
// speedup vs baseline: 1.5022x; 1.5022x over previous
#include <cuda_runtime.h>
#include <cuda_fp16.h>
#include <math.h>
#include <stdint.h>

#define EXPERTS 8
#define HID     2048
#define IEXP    1408
#define SIEXP   2816
#define TTOK    4096
#define NPAIR   8192

// ---------------- scratch ----------------
__device__ int    g_cnt[EXPERTS];
__device__ int    g_tok[EXPERTS * NPAIR];
__device__ int    g_pid[EXPERTS * NPAIR];
__device__ float  g_pw [EXPERTS * NPAIR];
__device__ __half g_acth[11534336];       // [TTOK][SIEXP] then [NPAIR][IEXP]
__device__ float  g_pairout[NPAIR * HID];
// fp16 copies: X as-is, weights TRANSPOSED to [N][K]
__device__ __half g_xh  [TTOK * HID];
__device__ __half g_w1h [EXPERTS * 2 * IEXP * HID];   // [E][2I][H]
__device__ __half g_w2h [EXPERTS * HID * IEXP];       // [E][H][I]
__device__ __half g_ws1h[2 * SIEXP * HID];            // [2SI][H]
__device__ __half g_ws2h[HID * SIEXP];                // [H][SI]

__device__ __forceinline__ float silu_f(float a) { return a / (1.0f + expf(-a)); }

__device__ __forceinline__ void mma16(float& d0, float& d1, float& d2, float& d3,
                                      uint32_t a0, uint32_t a1, uint32_t a2, uint32_t a3,
                                      uint32_t b0, uint32_t b1) {
    asm volatile(
        "mma.sync.aligned.m16n8k16.row.col.f32.f16.f16.f32 "
        "{%0,%1,%2,%3},{%4,%5,%6,%7},{%8,%9},{%0,%1,%2,%3};"
        : "+f"(d0), "+f"(d1), "+f"(d2), "+f"(d3)
        : "r"(a0), "r"(a1), "r"(a2), "r"(a3), "r"(b0), "r"(b1));
}

__device__ __forceinline__ void cpa16s(uint32_t dst, const void* src) {
    asm volatile("cp.async.cg.shared.global [%0], [%1], 16;" :: "r"(dst), "l"(src));
}
#define CP_COMMIT() asm volatile("cp.async.commit_group;")
#define CP_WAIT(N)  asm volatile("cp.async.wait_group %0;" :: "n"(N))

__device__ __forceinline__ uint32_t smem_u32(const void* p) {
    return (uint32_t)__cvta_generic_to_shared(p);
}

// ---------------- pre-processing ----------------
__global__ void tohalf_kernel(const float4* __restrict__ src, uint2* __restrict__ dst, int n4) {
    int i = blockIdx.x * blockDim.x + threadIdx.x;
    if (i < n4) {
        float4 v = src[i];
        __half2 lo = __floats2half2_rn(v.x, v.y);
        __half2 hi = __floats2half2_rn(v.z, v.w);
        uint2 o;
        o.x = *(uint32_t*)&lo; o.y = *(uint32_t*)&hi;
        dst[i] = o;
    }
}

// transpose [K][N] fp32 -> [N][K] fp16; grid (N/32, K/32, batch), block (32,8)
__global__ void transpose_half_kernel(const float* __restrict__ src, __half* __restrict__ dst,
                                      int K, int N, long long sStride, long long dStride) {
    __shared__ float t[32][33];
    src += (size_t)blockIdx.z * sStride;
    dst += (size_t)blockIdx.z * dStride;
    int k0 = blockIdx.y * 32, n0 = blockIdx.x * 32;
    int tx = threadIdx.x, ty = threadIdx.y;
    #pragma unroll
    for (int i = 0; i < 32; i += 8)
        t[ty + i][tx] = src[(size_t)(k0 + ty + i) * N + n0 + tx];
    __syncthreads();
    #pragma unroll
    for (int i = 0; i < 32; i += 8)
        dst[(size_t)(n0 + ty + i) * K + k0 + tx] = __float2half(t[tx][ty + i]);
}

// ---------------- routing ----------------
__global__ void zero_cnt_kernel() {
    if (threadIdx.x < EXPERTS) g_cnt[threadIdx.x] = 0;
}

__global__ void route_kernel(const int* __restrict__ topk_idx,
                             const float* __restrict__ topk_w) {
    int p = blockIdx.x * blockDim.x + threadIdx.x;
    if (p < NPAIR) {
        int e = topk_idx[p];
        int pos = atomicAdd(&g_cnt[e], 1);
        g_tok[e * NPAIR + pos] = p >> 1;
        g_pid[e * NPAIR + pos] = p;
        g_pw [e * NPAIR + pos] = topk_w[p];
    }
}

// =====================================================================
// fp16 HMMA GEMMs. Smem tiles: 128 rows x 64 halfs (128B data) padded to
// 144B/row (36 words -> conflict-free 4g+t bank pattern). K-chunk = 64.
// 2-stage cp.async ring (R13-proven pipeline).
// =====================================================================
#define TILE_B   18432           // 128 * 144
#define BUF_B    (2 * TILE_B)    // A + B tile
#define SMEM_B   (2 * BUF_B)     // 2 stages

// ---------------- GEMM1: h = silu(A@Wg) * (A@Wu) ----------------
// CTA: 128 M x 64 N. 8 warps = 4(M) x 2(N). Warp 32M x 32N per half.
// B tile rows: [0,64) = gate rows n0.., [64,128) = up rows IN+n0..
template<int ROUTED>
__global__ __launch_bounds__(256) void g1fp16(const __half* __restrict__ A,
                                              const __half* __restrict__ Wt) {
    const int IN = ROUTED ? IEXP : SIEXP;
    const int m0 = blockIdx.y * 128;
    const int n0 = blockIdx.x * 64;

    extern __shared__ char dsm[];
    __shared__ int s_tok[128];
    __shared__ int s_pid[128];

    const int tid = threadIdx.x;
    if (ROUTED) {
        const int e = blockIdx.z;
        const int cnt = g_cnt[e];
        if (m0 >= cnt) return;
        Wt += (size_t)e * 2 * IEXP * HID;
        if (tid < 128) {
            int r = m0 + tid;
            bool ok = r < cnt;
            s_tok[tid] = ok ? g_tok[e * NPAIR + r] : 0;
            s_pid[tid] = ok ? g_pid[e * NPAIR + r] : -1;
        }
        __syncthreads();
    }

    const int lane = tid & 31, w = tid >> 5;
    const int gid = lane >> 2, tig = lane & 3;
    const int wm = w & 3, wn = w >> 2;

    // per-thread source row pointers for the 4 A-chunks and 4 B-chunks
    const __half* aro[4];
    const __half* bro[4];
    #pragma unroll
    for (int p = 0; p < 4; p++) {
        int idx = p * 256 + tid;
        int row = idx >> 3;
        aro[p] = A + (size_t)(ROUTED ? s_tok[row] : (m0 + row)) * HID;
        int br = row;  // 0..127
        int gr = (br < 64) ? (n0 + br) : (IN + n0 + (br - 64));
        bro[p] = Wt + (size_t)gr * HID;
    }

    float accA[2][4][4] = {}, accB[2][4][4] = {};
    const uint32_t dbase = smem_u32(dsm);

    #define G1_ISSUE(buf, k0)                                                \
    {                                                                        \
        uint32_t Au = dbase + (buf) * BUF_B;                                 \
        uint32_t Bu = Au + TILE_B;                                           \
        _Pragma("unroll")                                                    \
        for (int p = 0; p < 4; p++) {                                        \
            int idx = p * 256 + tid;                                         \
            int row = idx >> 3, c = idx & 7;                                 \
            cpa16s(Au + row * 144 + c * 16, aro[p] + (k0) + c * 8);          \
            cpa16s(Bu + row * 144 + c * 16, bro[p] + (k0) + c * 8);          \
        }                                                                    \
        CP_COMMIT();                                                         \
    }

    G1_ISSUE(0, 0);
    G1_ISSUE(1, 64);

    int buf = 0;
    for (int k0 = 0; k0 < HID; k0 += 64) {
        CP_WAIT(1);
        __syncthreads();

        const uint32_t* As = (const uint32_t*)(dsm + buf * BUF_B);
        const uint32_t* Bs = As + 128 * 36;

        #pragma unroll
        for (int ks = 0; ks < 4; ks++) {
            const int kk = ks * 8;
            uint32_t af[2][4];
            #pragma unroll
            for (int mt = 0; mt < 2; mt++) {
                int mr = wm * 32 + mt * 16;
                af[mt][0] = As[(mr + gid    ) * 36 + kk + tig];
                af[mt][1] = As[(mr + gid + 8) * 36 + kk + tig];
                af[mt][2] = As[(mr + gid    ) * 36 + kk + tig + 4];
                af[mt][3] = As[(mr + gid + 8) * 36 + kk + tig + 4];
            }
            #pragma unroll
            for (int nt = 0; nt < 4; nt++) {
                int nbg = wn * 32 + nt * 8 + gid;        // gate row
                uint32_t ba0 = Bs[nbg * 36 + kk + tig];
                uint32_t ba1 = Bs[nbg * 36 + kk + tig + 4];
                uint32_t bb0 = Bs[(64 + nbg) * 36 + kk + tig];
                uint32_t bb1 = Bs[(64 + nbg) * 36 + kk + tig + 4];
                #pragma unroll
                for (int mt = 0; mt < 2; mt++) {
                    mma16(accA[mt][nt][0], accA[mt][nt][1], accA[mt][nt][2], accA[mt][nt][3],
                          af[mt][0], af[mt][1], af[mt][2], af[mt][3], ba0, ba1);
                    mma16(accB[mt][nt][0], accB[mt][nt][1], accB[mt][nt][2], accB[mt][nt][3],
                          af[mt][0], af[mt][1], af[mt][2], af[mt][3], bb0, bb1);
                }
            }
        }
        __syncthreads();

        int kn = k0 + 128;
        if (kn < HID) { G1_ISSUE(buf, kn); }
        else          { CP_COMMIT(); }
        buf ^= 1;
    }
    #undef G1_ISSUE

    // epilogue: swiglu -> g_acth (half2 stores, cols 2tig,2tig+1 adjacent)
    #pragma unroll
    for (int mt = 0; mt < 2; mt++) {
        int lm0 = wm * 32 + mt * 16 + gid;
        int lm1 = lm0 + 8;
        int row0, row1;
        if (ROUTED) { row0 = s_pid[lm0]; row1 = s_pid[lm1]; }
        else        { row0 = m0 + lm0;   row1 = m0 + lm1; }
        #pragma unroll
        for (int nt = 0; nt < 4; nt++) {
            int col = n0 + wn * 32 + nt * 8 + 2 * tig;
            if (row0 >= 0) {
                __half2 v = __floats2half2_rn(
                    silu_f(accA[mt][nt][0]) * accB[mt][nt][0],
                    silu_f(accA[mt][nt][1]) * accB[mt][nt][1]);
                *(__half2*)&g_acth[(size_t)row0 * IN + col] = v;
            }
            if (row1 >= 0) {
                __half2 v = __floats2half2_rn(
                    silu_f(accA[mt][nt][2]) * accB[mt][nt][2],
                    silu_f(accA[mt][nt][3]) * accB[mt][nt][3]);
                *(__half2*)&g_acth[(size_t)row1 * IN + col] = v;
            }
        }
    }
}

// ---------------- GEMM2: C = act @ Wt^T (+ scale, pid scatter) ----------------
// CTA: 128 M x 128 N. 8 warps = 2(M) x 4(N). Warp 64M x 32N.
template<int ROUTED>
__global__ __launch_bounds__(256) void g2fp16(const __half* __restrict__ Wt,
                                              float* __restrict__ C) {
    const int IN = ROUTED ? IEXP : SIEXP;   // K depth
    const int m0 = blockIdx.y * 128;
    const int n0 = blockIdx.x * 128;

    extern __shared__ char dsm[];
    __shared__ int   s_pid[128];
    __shared__ float s_w[128];

    const int tid = threadIdx.x;
    float* Cw = ROUTED ? g_pairout : C;
    if (ROUTED) {
        const int e = blockIdx.z;
        const int cnt = g_cnt[e];
        if (m0 >= cnt) return;
        Wt += (size_t)e * HID * IEXP;
        if (tid < 128) {
            int r = m0 + tid;
            bool ok = r < cnt;
            s_pid[tid] = ok ? g_pid[e * NPAIR + r] : -1;
            s_w[tid]   = ok ? g_pw [e * NPAIR + r] : 0.f;
        }
        __syncthreads();
    }

    const int lane = tid & 31, w = tid >> 5;
    const int gid = lane >> 2, tig = lane & 3;
    const int wm = w & 1, wn = w >> 1;

    const __half* aro[4];
    const __half* bro[4];
    #pragma unroll
    for (int p = 0; p < 4; p++) {
        int idx = p * 256 + tid;
        int row = idx >> 3;
        int ar = ROUTED ? (s_pid[row] >= 0 ? s_pid[row] : 0) : (m0 + row);
        aro[p] = g_acth + (size_t)ar * IN;
        bro[p] = Wt + (size_t)(n0 + row) * IN;
    }

    float acc[4][4][4] = {};
    const uint32_t dbase = smem_u32(dsm);

    #define G2_ISSUE(buf, k0)                                                \
    {                                                                        \
        uint32_t Au = dbase + (buf) * BUF_B;                                 \
        uint32_t Bu = Au + TILE_B;                                           \
        _Pragma("unroll")                                                    \
        for (int p = 0; p < 4; p++) {                                        \
            int idx = p * 256 + tid;                                         \
            int row = idx >> 3, c = idx & 7;                                 \
            cpa16s(Au + row * 144 + c * 16, aro[p] + (k0) + c * 8);          \
            cpa16s(Bu + row * 144 + c * 16, bro[p] + (k0) + c * 8);          \
        }                                                                    \
        CP_COMMIT();                                                         \
    }

    G2_ISSUE(0, 0);
    G2_ISSUE(1, 64);

    int buf = 0;
    for (int k0 = 0; k0 < IN; k0 += 64) {
        CP_WAIT(1);
        __syncthreads();

        const uint32_t* As = (const uint32_t*)(dsm + buf * BUF_B);
        const uint32_t* Bs = As + 128 * 36;

        #pragma unroll
        for (int ks = 0; ks < 4; ks++) {
            const int kk = ks * 8;
            uint32_t af[4][4];
            #pragma unroll
            for (int mt = 0; mt < 4; mt++) {
                int mr = wm * 64 + mt * 16;
                af[mt][0] = As[(mr + gid    ) * 36 + kk + tig];
                af[mt][1] = As[(mr + gid + 8) * 36 + kk + tig];
                af[mt][2] = As[(mr + gid    ) * 36 + kk + tig + 4];
                af[mt][3] = As[(mr + gid + 8) * 36 + kk + tig + 4];
            }
            #pragma unroll
            for (int nt = 0; nt < 4; nt++) {
                int nb = wn * 32 + nt * 8 + gid;
                uint32_t b0 = Bs[nb * 36 + kk + tig];
                uint32_t b1 = Bs[nb * 36 + kk + tig + 4];
                #pragma unroll
                for (int mt = 0; mt < 4; mt++)
                    mma16(acc[mt][nt][0], acc[mt][nt][1], acc[mt][nt][2], acc[mt][nt][3],
                          af[mt][0], af[mt][1], af[mt][2], af[mt][3], b0, b1);
            }
        }
        __syncthreads();

        int kn = k0 + 128;
        if (kn < IN) { G2_ISSUE(buf, kn); }
        else         { CP_COMMIT(); }
        buf ^= 1;
    }
    #undef G2_ISSUE

    // epilogue
    #pragma unroll
    for (int mt = 0; mt < 4; mt++) {
        int lm0 = wm * 64 + mt * 16 + gid;
        int lm1 = lm0 + 8;
        int row0, row1; float w0 = 1.f, w1 = 1.f;
        if (ROUTED) {
            row0 = s_pid[lm0]; row1 = s_pid[lm1];
            w0 = s_w[lm0]; w1 = s_w[lm1];
        } else { row0 = m0 + lm0; row1 = m0 + lm1; }
        #pragma unroll
        for (int nt = 0; nt < 4; nt++) {
            int col = n0 + wn * 32 + nt * 8 + 2 * tig;
            if (row0 >= 0) {
                float2 v; v.x = w0 * acc[mt][nt][0]; v.y = w0 * acc[mt][nt][1];
                *(float2*)&Cw[(size_t)row0 * HID + col] = v;
            }
            if (row1 >= 0) {
                float2 v; v.x = w1 * acc[mt][nt][2]; v.y = w1 * acc[mt][nt][3];
                *(float2*)&Cw[(size_t)row1 * HID + col] = v;
            }
        }
    }
}

// ---------------- combine ----------------
__global__ void combine_kernel(float* __restrict__ out) {
    int v = blockIdx.x * blockDim.x + threadIdx.x;
    const int HV = HID / 4;
    if (v < TTOK * HV) {
        int t = v / HV;
        int h4 = v - t * HV;
        float4 o  = ((float4*)out)[v];
        float4 p0 = ((const float4*)g_pairout)[(size_t)(2 * t) * HV + h4];
        float4 p1 = ((const float4*)g_pairout)[(size_t)(2 * t + 1) * HV + h4];
        o.x += p0.x + p1.x; o.y += p0.y + p1.y;
        o.z += p0.z + p1.z; o.w += p0.w + p1.w;
        ((float4*)out)[v] = o;
    }
}

// ---------------- launcher ----------------
extern "C" void kernel_launch(void* const* d_in, const int* in_sizes, int n_in,
                              void* d_out, int out_size) {
    const float* x        = (const float*)d_in[0];  // [T, H]
    const float* topk_w   = (const float*)d_in[1];  // [T, 2]
    const float* W1       = (const float*)d_in[2];  // [E, H, 2I]
    const float* W2       = (const float*)d_in[3];  // [E, I, H]
    const float* Ws1      = (const float*)d_in[4];  // [H, 2SI]
    const float* Ws2      = (const float*)d_in[5];  // [SI, H]
    const int*   topk_idx = (const int*)d_in[6];    // [T, 2]
    float* out = (float*)d_out;                     // [T, H]

    (void)in_sizes; (void)n_in; (void)out_size;

    __half *xh, *w1h, *w2h, *ws1h, *ws2h;
    cudaGetSymbolAddress((void**)&xh,   g_xh);
    cudaGetSymbolAddress((void**)&w1h,  g_w1h);
    cudaGetSymbolAddress((void**)&w2h,  g_w2h);
    cudaGetSymbolAddress((void**)&ws1h, g_ws1h);
    cudaGetSymbolAddress((void**)&ws2h, g_ws2h);

    cudaFuncSetAttribute(g1fp16<0>, cudaFuncAttributeMaxDynamicSharedMemorySize, SMEM_B);
    cudaFuncSetAttribute(g1fp16<1>, cudaFuncAttributeMaxDynamicSharedMemorySize, SMEM_B);
    cudaFuncSetAttribute(g2fp16<0>, cudaFuncAttributeMaxDynamicSharedMemorySize, SMEM_B);
    cudaFuncSetAttribute(g2fp16<1>, cudaFuncAttributeMaxDynamicSharedMemorySize, SMEM_B);

    // X -> fp16; weights -> fp16 transposed [N][K]
    const int n4x = TTOK * HID / 4;
    tohalf_kernel<<<(n4x + 255) / 256, 256>>>((const float4*)x, (uint2*)xh, n4x);
    {
        dim3 blk(32, 8);
        transpose_half_kernel<<<dim3(2 * IEXP / 32, HID / 32, EXPERTS), blk>>>(
            W1, w1h, HID, 2 * IEXP, (long long)HID * 2 * IEXP, (long long)HID * 2 * IEXP);
        transpose_half_kernel<<<dim3(HID / 32, IEXP / 32, EXPERTS), blk>>>(
            W2, w2h, IEXP, HID, (long long)IEXP * HID, (long long)IEXP * HID);
        transpose_half_kernel<<<dim3(2 * SIEXP / 32, HID / 32, 1), blk>>>(
            Ws1, ws1h, HID, 2 * SIEXP, 0, 0);
        transpose_half_kernel<<<dim3(HID / 32, SIEXP / 32, 1), blk>>>(
            Ws2, ws2h, SIEXP, HID, 0, 0);
    }

    zero_cnt_kernel<<<1, 32>>>();
    route_kernel<<<NPAIR / 256, 256>>>(topk_idx, topk_w);

    // shared expert path
    g1fp16<0><<<dim3(SIEXP / 64, TTOK / 128), 256, SMEM_B>>>(xh, ws1h);
    g2fp16<0><<<dim3(HID / 128, TTOK / 128), 256, SMEM_B>>>(ws2h, out);

    // routed expert path (g_acth reused after shared GEMM2 consumed it)
    g1fp16<1><<<dim3(IEXP / 64, NPAIR / 128, EXPERTS), 256, SMEM_B>>>(xh, w1h);
    g2fp16<1><<<dim3(HID / 128, NPAIR / 128, EXPERTS), 256, SMEM_B>>>(w2h, nullptr);

    combine_kernel<<<(TTOK * (HID / 4) + 255) / 256, 256>>>(out);
}

// round 17
// speedup vs baseline: 1.8270x; 1.2162x over previous
#include <cuda_runtime.h>
#include <cuda_fp16.h>
#include <math.h>
#include <stdint.h>

#define EXPERTS 8
#define HID     2048
#define IEXP    1408
#define SIEXP   2816
#define TTOK    4096
#define NPAIR   8192

// ---------------- scratch ----------------
__device__ int    g_cnt[EXPERTS];
__device__ int    g_tok[EXPERTS * NPAIR];
__device__ int    g_pid[EXPERTS * NPAIR];
__device__ float  g_pw [EXPERTS * NPAIR];
__device__ __half g_acth[11534336];       // [TTOK][SIEXP] then [NPAIR][IEXP]
__device__ float  g_pairout[NPAIR * HID];
// fp16 copies: X as-is, weights TRANSPOSED to [N][K]
__device__ __half g_xh  [TTOK * HID];
__device__ __half g_w1h [EXPERTS * 2 * IEXP * HID];   // [E][2I][H]
__device__ __half g_w2h [EXPERTS * HID * IEXP];       // [E][H][I]
__device__ __half g_ws1h[2 * SIEXP * HID];            // [2SI][H]
__device__ __half g_ws2h[HID * SIEXP];                // [H][SI]

__device__ __forceinline__ float silu_f(float a) { return a / (1.0f + expf(-a)); }

__device__ __forceinline__ void mma16(float& d0, float& d1, float& d2, float& d3,
                                      uint32_t a0, uint32_t a1, uint32_t a2, uint32_t a3,
                                      uint32_t b0, uint32_t b1) {
    asm volatile(
        "mma.sync.aligned.m16n8k16.row.col.f32.f16.f16.f32 "
        "{%0,%1,%2,%3},{%4,%5,%6,%7},{%8,%9},{%0,%1,%2,%3};"
        : "+f"(d0), "+f"(d1), "+f"(d2), "+f"(d3)
        : "r"(a0), "r"(a1), "r"(a2), "r"(a3), "r"(b0), "r"(b1));
}

__device__ __forceinline__ void ldsm_x4(uint32_t& r0, uint32_t& r1, uint32_t& r2, uint32_t& r3,
                                        uint32_t addr) {
    asm volatile("ldmatrix.sync.aligned.m8n8.x4.shared.b16 {%0,%1,%2,%3}, [%4];"
        : "=r"(r0), "=r"(r1), "=r"(r2), "=r"(r3) : "r"(addr));
}

__device__ __forceinline__ void cpa16s(uint32_t dst, const void* src) {
    asm volatile("cp.async.cg.shared.global [%0], [%1], 16;" :: "r"(dst), "l"(src));
}
#define CP_COMMIT() asm volatile("cp.async.commit_group;")
#define CP_WAIT(N)  asm volatile("cp.async.wait_group %0;" :: "n"(N))

__device__ __forceinline__ uint32_t smem_u32(const void* p) {
    return (uint32_t)__cvta_generic_to_shared(p);
}

// ---------------- pre-processing ----------------
__global__ void tohalf_kernel(const float4* __restrict__ src, uint2* __restrict__ dst, int n4) {
    int i = blockIdx.x * blockDim.x + threadIdx.x;
    if (i < n4) {
        float4 v = src[i];
        __half2 lo = __floats2half2_rn(v.x, v.y);
        __half2 hi = __floats2half2_rn(v.z, v.w);
        uint2 o;
        o.x = *(uint32_t*)&lo; o.y = *(uint32_t*)&hi;
        dst[i] = o;
    }
}

// transpose [K][N] fp32 -> [N][K] fp16; grid (N/32, K/32, batch), block (32,8)
__global__ void transpose_half_kernel(const float* __restrict__ src, __half* __restrict__ dst,
                                      int K, int N, long long sStride, long long dStride) {
    __shared__ float t[32][33];
    src += (size_t)blockIdx.z * sStride;
    dst += (size_t)blockIdx.z * dStride;
    int k0 = blockIdx.y * 32, n0 = blockIdx.x * 32;
    int tx = threadIdx.x, ty = threadIdx.y;
    #pragma unroll
    for (int i = 0; i < 32; i += 8)
        t[ty + i][tx] = src[(size_t)(k0 + ty + i) * N + n0 + tx];
    __syncthreads();
    #pragma unroll
    for (int i = 0; i < 32; i += 8)
        dst[(size_t)(n0 + ty + i) * K + k0 + tx] = __float2half(t[tx][ty + i]);
}

// ---------------- routing ----------------
__global__ void zero_cnt_kernel() {
    if (threadIdx.x < EXPERTS) g_cnt[threadIdx.x] = 0;
}

__global__ void route_kernel(const int* __restrict__ topk_idx,
                             const float* __restrict__ topk_w) {
    int p = blockIdx.x * blockDim.x + threadIdx.x;
    if (p < NPAIR) {
        int e = topk_idx[p];
        int pos = atomicAdd(&g_cnt[e], 1);
        g_tok[e * NPAIR + pos] = p >> 1;
        g_pid[e * NPAIR + pos] = p;
        g_pw [e * NPAIR + pos] = topk_w[p];
    }
}

// =====================================================================
// fp16 HMMA GEMMs with ldmatrix fragment loads.
// Smem tiles: 128 rows x 64 halfs, 144B/row pitch. K-chunk = 64.
// 2-stage cp.async ring.
// Per-thread ldmatrix lane mapping (t = lane):
//   A (x4, one 16x16 frag):  row = mr + (t&15), word = kk + (t>>4)*4
//   B (x4, two n8k16 frags): row = base + ((t>>4)<<3) + (t&7),
//                            word = kk + ((t>>3)&1)*4
//   -> regs (a0,a1,a2,a3) / (nt0.b0, nt0.b1, nt1.b0, nt1.b1)
// =====================================================================
#define TILE_B   18432           // 128 * 144
#define BUF_B    (2 * TILE_B)    // A + B tile
#define SMEM_B   (2 * BUF_B)     // 2 stages

// ---------------- GEMM1: h = silu(A@Wg) * (A@Wu) ----------------
template<int ROUTED>
__global__ __launch_bounds__(256) void g1fp16(const __half* __restrict__ A,
                                              const __half* __restrict__ Wt) {
    const int IN = ROUTED ? IEXP : SIEXP;
    const int m0 = blockIdx.y * 128;
    const int n0 = blockIdx.x * 64;

    extern __shared__ char dsm[];
    __shared__ int s_tok[128];
    __shared__ int s_pid[128];

    const int tid = threadIdx.x;
    if (ROUTED) {
        const int e = blockIdx.z;
        const int cnt = g_cnt[e];
        if (m0 >= cnt) return;
        Wt += (size_t)e * 2 * IEXP * HID;
        if (tid < 128) {
            int r = m0 + tid;
            bool ok = r < cnt;
            s_tok[tid] = ok ? g_tok[e * NPAIR + r] : 0;
            s_pid[tid] = ok ? g_pid[e * NPAIR + r] : -1;
        }
        __syncthreads();
    }

    const int lane = tid & 31, w = tid >> 5;
    const int gid = lane >> 2, tig = lane & 3;
    const int wm = w & 3, wn = w >> 2;

    const __half* aro[4];
    const __half* bro[4];
    #pragma unroll
    for (int p = 0; p < 4; p++) {
        int idx = p * 256 + tid;
        int row = idx >> 3;
        aro[p] = A + (size_t)(ROUTED ? s_tok[row] : (m0 + row)) * HID;
        int gr = (row < 64) ? (n0 + row) : (IN + n0 + (row - 64));
        bro[p] = Wt + (size_t)gr * HID;
    }

    float accA[2][4][4] = {}, accB[2][4][4] = {};
    const uint32_t dbase = smem_u32(dsm);

    // ldmatrix per-thread byte offsets within a tile
    const uint32_t a_thr = (uint32_t)((lane & 15) * 144 + (lane >> 4) * 16);
    const uint32_t b_thr = (uint32_t)((((lane >> 4) << 3) + (lane & 7)) * 144 + ((lane >> 3) & 1) * 16);

    #define G1_ISSUE(buf, k0)                                                \
    {                                                                        \
        uint32_t Au = dbase + (buf) * BUF_B;                                 \
        uint32_t Bu = Au + TILE_B;                                           \
        _Pragma("unroll")                                                    \
        for (int p = 0; p < 4; p++) {                                        \
            int idx = p * 256 + tid;                                         \
            int row = idx >> 3, c = idx & 7;                                 \
            cpa16s(Au + row * 144 + c * 16, aro[p] + (k0) + c * 8);          \
            cpa16s(Bu + row * 144 + c * 16, bro[p] + (k0) + c * 8);          \
        }                                                                    \
        CP_COMMIT();                                                         \
    }

    G1_ISSUE(0, 0);
    G1_ISSUE(1, 64);

    int buf = 0;
    for (int k0 = 0; k0 < HID; k0 += 64) {
        CP_WAIT(1);
        __syncthreads();

        const uint32_t Au = dbase + buf * BUF_B;
        const uint32_t Bu = Au + TILE_B;

        #pragma unroll
        for (int ks = 0; ks < 4; ks++) {
            const uint32_t kb = (uint32_t)(ks * 32);  // 8 words = 32 bytes
            uint32_t af[2][4], bg[2][4], bu[2][4];
            #pragma unroll
            for (int mt = 0; mt < 2; mt++)
                ldsm_x4(af[mt][0], af[mt][1], af[mt][2], af[mt][3],
                        Au + (uint32_t)((wm * 32 + mt * 16) * 144) + a_thr + kb);
            #pragma unroll
            for (int tp = 0; tp < 2; tp++) {
                ldsm_x4(bg[tp][0], bg[tp][1], bg[tp][2], bg[tp][3],
                        Bu + (uint32_t)((wn * 32 + tp * 16) * 144) + b_thr + kb);
                ldsm_x4(bu[tp][0], bu[tp][1], bu[tp][2], bu[tp][3],
                        Bu + (uint32_t)((64 + wn * 32 + tp * 16) * 144) + b_thr + kb);
            }
            #pragma unroll
            for (int nt = 0; nt < 4; nt++) {
                uint32_t ba0 = bg[nt >> 1][(nt & 1) * 2], ba1 = bg[nt >> 1][(nt & 1) * 2 + 1];
                uint32_t bb0 = bu[nt >> 1][(nt & 1) * 2], bb1 = bu[nt >> 1][(nt & 1) * 2 + 1];
                #pragma unroll
                for (int mt = 0; mt < 2; mt++) {
                    mma16(accA[mt][nt][0], accA[mt][nt][1], accA[mt][nt][2], accA[mt][nt][3],
                          af[mt][0], af[mt][1], af[mt][2], af[mt][3], ba0, ba1);
                    mma16(accB[mt][nt][0], accB[mt][nt][1], accB[mt][nt][2], accB[mt][nt][3],
                          af[mt][0], af[mt][1], af[mt][2], af[mt][3], bb0, bb1);
                }
            }
        }
        __syncthreads();

        int kn = k0 + 128;
        if (kn < HID) { G1_ISSUE(buf, kn); }
        else          { CP_COMMIT(); }
        buf ^= 1;
    }
    #undef G1_ISSUE

    // epilogue: swiglu -> g_acth
    #pragma unroll
    for (int mt = 0; mt < 2; mt++) {
        int lm0 = wm * 32 + mt * 16 + gid;
        int lm1 = lm0 + 8;
        int row0, row1;
        if (ROUTED) { row0 = s_pid[lm0]; row1 = s_pid[lm1]; }
        else        { row0 = m0 + lm0;   row1 = m0 + lm1; }
        #pragma unroll
        for (int nt = 0; nt < 4; nt++) {
            int col = n0 + wn * 32 + nt * 8 + 2 * tig;
            if (row0 >= 0) {
                __half2 v = __floats2half2_rn(
                    silu_f(accA[mt][nt][0]) * accB[mt][nt][0],
                    silu_f(accA[mt][nt][1]) * accB[mt][nt][1]);
                *(__half2*)&g_acth[(size_t)row0 * IN + col] = v;
            }
            if (row1 >= 0) {
                __half2 v = __floats2half2_rn(
                    silu_f(accA[mt][nt][2]) * accB[mt][nt][2],
                    silu_f(accA[mt][nt][3]) * accB[mt][nt][3]);
                *(__half2*)&g_acth[(size_t)row1 * IN + col] = v;
            }
        }
    }
}

// ---------------- GEMM2: C = act @ Wt^T (+ scale, pid scatter) ----------------
template<int ROUTED>
__global__ __launch_bounds__(256) void g2fp16(const __half* __restrict__ Wt,
                                              float* __restrict__ C) {
    const int IN = ROUTED ? IEXP : SIEXP;   // K depth
    const int m0 = blockIdx.y * 128;
    const int n0 = blockIdx.x * 128;

    extern __shared__ char dsm[];
    __shared__ int   s_pid[128];
    __shared__ float s_w[128];

    const int tid = threadIdx.x;
    float* Cw = ROUTED ? g_pairout : C;
    if (ROUTED) {
        const int e = blockIdx.z;
        const int cnt = g_cnt[e];
        if (m0 >= cnt) return;
        Wt += (size_t)e * HID * IEXP;
        if (tid < 128) {
            int r = m0 + tid;
            bool ok = r < cnt;
            s_pid[tid] = ok ? g_pid[e * NPAIR + r] : -1;
            s_w[tid]   = ok ? g_pw [e * NPAIR + r] : 0.f;
        }
        __syncthreads();
    }

    const int lane = tid & 31, w = tid >> 5;
    const int gid = lane >> 2, tig = lane & 3;
    const int wm = w & 1, wn = w >> 1;

    const __half* aro[4];
    const __half* bro[4];
    #pragma unroll
    for (int p = 0; p < 4; p++) {
        int idx = p * 256 + tid;
        int row = idx >> 3;
        int ar = ROUTED ? (s_pid[row] >= 0 ? s_pid[row] : 0) : (m0 + row);
        aro[p] = g_acth + (size_t)ar * IN;
        bro[p] = Wt + (size_t)(n0 + row) * IN;
    }

    float acc[4][4][4] = {};
    const uint32_t dbase = smem_u32(dsm);

    const uint32_t a_thr = (uint32_t)((lane & 15) * 144 + (lane >> 4) * 16);
    const uint32_t b_thr = (uint32_t)((((lane >> 4) << 3) + (lane & 7)) * 144 + ((lane >> 3) & 1) * 16);

    #define G2_ISSUE(buf, k0)                                                \
    {                                                                        \
        uint32_t Au = dbase + (buf) * BUF_B;                                 \
        uint32_t Bu = Au + TILE_B;                                           \
        _Pragma("unroll")                                                    \
        for (int p = 0; p < 4; p++) {                                        \
            int idx = p * 256 + tid;                                         \
            int row = idx >> 3, c = idx & 7;                                 \
            cpa16s(Au + row * 144 + c * 16, aro[p] + (k0) + c * 8);          \
            cpa16s(Bu + row * 144 + c * 16, bro[p] + (k0) + c * 8);          \
        }                                                                    \
        CP_COMMIT();                                                         \
    }

    G2_ISSUE(0, 0);
    G2_ISSUE(1, 64);

    int buf = 0;
    for (int k0 = 0; k0 < IN; k0 += 64) {
        CP_WAIT(1);
        __syncthreads();

        const uint32_t Au = dbase + buf * BUF_B;
        const uint32_t Bu = Au + TILE_B;

        #pragma unroll
        for (int ks = 0; ks < 4; ks++) {
            const uint32_t kb = (uint32_t)(ks * 32);
            uint32_t af[4][4], bf[2][4];
            #pragma unroll
            for (int mt = 0; mt < 4; mt++)
                ldsm_x4(af[mt][0], af[mt][1], af[mt][2], af[mt][3],
                        Au + (uint32_t)((wm * 64 + mt * 16) * 144) + a_thr + kb);
            #pragma unroll
            for (int tp = 0; tp < 2; tp++)
                ldsm_x4(bf[tp][0], bf[tp][1], bf[tp][2], bf[tp][3],
                        Bu + (uint32_t)((wn * 32 + tp * 16) * 144) + b_thr + kb);
            #pragma unroll
            for (int nt = 0; nt < 4; nt++) {
                uint32_t b0 = bf[nt >> 1][(nt & 1) * 2], b1 = bf[nt >> 1][(nt & 1) * 2 + 1];
                #pragma unroll
                for (int mt = 0; mt < 4; mt++)
                    mma16(acc[mt][nt][0], acc[mt][nt][1], acc[mt][nt][2], acc[mt][nt][3],
                          af[mt][0], af[mt][1], af[mt][2], af[mt][3], b0, b1);
            }
        }
        __syncthreads();

        int kn = k0 + 128;
        if (kn < IN) { G2_ISSUE(buf, kn); }
        else         { CP_COMMIT(); }
        buf ^= 1;
    }
    #undef G2_ISSUE

    // epilogue
    #pragma unroll
    for (int mt = 0; mt < 4; mt++) {
        int lm0 = wm * 64 + mt * 16 + gid;
        int lm1 = lm0 + 8;
        int row0, row1; float w0 = 1.f, w1 = 1.f;
        if (ROUTED) {
            row0 = s_pid[lm0]; row1 = s_pid[lm1];
            w0 = s_w[lm0]; w1 = s_w[lm1];
        } else { row0 = m0 + lm0; row1 = m0 + lm1; }
        #pragma unroll
        for (int nt = 0; nt < 4; nt++) {
            int col = n0 + wn * 32 + nt * 8 + 2 * tig;
            if (row0 >= 0) {
                float2 v; v.x = w0 * acc[mt][nt][0]; v.y = w0 * acc[mt][nt][1];
                *(float2*)&Cw[(size_t)row0 * HID + col] = v;
            }
            if (row1 >= 0) {
                float2 v; v.x = w1 * acc[mt][nt][2]; v.y = w1 * acc[mt][nt][3];
                *(float2*)&Cw[(size_t)row1 * HID + col] = v;
            }
        }
    }
}

// ---------------- combine ----------------
__global__ void combine_kernel(float* __restrict__ out) {
    int v = blockIdx.x * blockDim.x + threadIdx.x;
    const int HV = HID / 4;
    if (v < TTOK * HV) {
        int t = v / HV;
        int h4 = v - t * HV;
        float4 o  = ((float4*)out)[v];
        float4 p0 = ((const float4*)g_pairout)[(size_t)(2 * t) * HV + h4];
        float4 p1 = ((const float4*)g_pairout)[(size_t)(2 * t + 1) * HV + h4];
        o.x += p0.x + p1.x; o.y += p0.y + p1.y;
        o.z += p0.z + p1.z; o.w += p0.w + p1.w;
        ((float4*)out)[v] = o;
    }
}

// ---------------- launcher ----------------
extern "C" void kernel_launch(void* const* d_in, const int* in_sizes, int n_in,
                              void* d_out, int out_size) {
    const float* x        = (const float*)d_in[0];  // [T, H]
    const float* topk_w   = (const float*)d_in[1];  // [T, 2]
    const float* W1       = (const float*)d_in[2];  // [E, H, 2I]
    const float* W2       = (const float*)d_in[3];  // [E, I, H]
    const float* Ws1      = (const float*)d_in[4];  // [H, 2SI]
    const float* Ws2      = (const float*)d_in[5];  // [SI, H]
    const int*   topk_idx = (const int*)d_in[6];    // [T, 2]
    float* out = (float*)d_out;                     // [T, H]

    (void)in_sizes; (void)n_in; (void)out_size;

    __half *xh, *w1h, *w2h, *ws1h, *ws2h;
    cudaGetSymbolAddress((void**)&xh,   g_xh);
    cudaGetSymbolAddress((void**)&w1h,  g_w1h);
    cudaGetSymbolAddress((void**)&w2h,  g_w2h);
    cudaGetSymbolAddress((void**)&ws1h, g_ws1h);
    cudaGetSymbolAddress((void**)&ws2h, g_ws2h);

    cudaFuncSetAttribute(g1fp16<0>, cudaFuncAttributeMaxDynamicSharedMemorySize, SMEM_B);
    cudaFuncSetAttribute(g1fp16<1>, cudaFuncAttributeMaxDynamicSharedMemorySize, SMEM_B);
    cudaFuncSetAttribute(g2fp16<0>, cudaFuncAttributeMaxDynamicSharedMemorySize, SMEM_B);
    cudaFuncSetAttribute(g2fp16<1>, cudaFuncAttributeMaxDynamicSharedMemorySize, SMEM_B);

    // X -> fp16; weights -> fp16 transposed [N][K]
    const int n4x = TTOK * HID / 4;
    tohalf_kernel<<<(n4x + 255) / 256, 256>>>((const float4*)x, (uint2*)xh, n4x);
    {
        dim3 blk(32, 8);
        transpose_half_kernel<<<dim3(2 * IEXP / 32, HID / 32, EXPERTS), blk>>>(
            W1, w1h, HID, 2 * IEXP, (long long)HID * 2 * IEXP, (long long)HID * 2 * IEXP);
        transpose_half_kernel<<<dim3(HID / 32, IEXP / 32, EXPERTS), blk>>>(
            W2, w2h, IEXP, HID, (long long)IEXP * HID, (long long)IEXP * HID);
        transpose_half_kernel<<<dim3(2 * SIEXP / 32, HID / 32, 1), blk>>>(
            Ws1, ws1h, HID, 2 * SIEXP, 0, 0);
        transpose_half_kernel<<<dim3(HID / 32, SIEXP / 32, 1), blk>>>(
            Ws2, ws2h, SIEXP, HID, 0, 0);
    }

    zero_cnt_kernel<<<1, 32>>>();
    route_kernel<<<NPAIR / 256, 256>>>(topk_idx, topk_w);

    // shared expert path
    g1fp16<0><<<dim3(SIEXP / 64, TTOK / 128), 256, SMEM_B>>>(xh, ws1h);
    g2fp16<0><<<dim3(HID / 128, TTOK / 128), 256, SMEM_B>>>(ws2h, out);

    // routed expert path (g_acth reused after shared GEMM2 consumed it)
    g1fp16<1><<<dim3(IEXP / 64, NPAIR / 128, EXPERTS), 256, SMEM_B>>>(xh, w1h);
    g2fp16<1><<<dim3(HID / 128, NPAIR / 128, EXPERTS), 256, SMEM_B>>>(w2h, nullptr);

    combine_kernel<<<(TTOK * (HID / 4) + 255) / 256, 256>>>(out);
}